// round 5
// baseline (speedup 1.0000x reference)
#include <cuda_runtime.h>
#include <cuda_bf16.h>

#define Hn 512
#define Bn 1024
#define Tn 512
#define On 10
#define NCTA 128
#define SHARD (Hn * 64)          // 32768 elems per ct-shard per buffer

#define SM_WHI 0                 // 8 chunks x [64 rows x 64 k] bf16 SW128 = 65536
#define SM_WLO 65536
#define SM_A   131072            // 4 bufs x (hi 8KB + lo 8KB)
#define SM_WB  196608            // float2[64] {W_hx, b_h}
#define SM_XS  197120            // float[64]
#define SM_TOTAL 197376

__device__ __align__(16) __nv_bfloat16 g_hhi[2][16 * SHARD];  // [buf][ct*SHARD + k*64 + b]
__device__ __align__(16) __nv_bfloat16 g_hlo[2][16 * SHARD];
__device__ unsigned g_flag[16][8];          // publish count per (ct, chunk); reset at end
__device__ unsigned g_bar_count = 0;
__device__ unsigned g_bar_gen   = 0;

static __device__ __forceinline__ unsigned smem_u32(const void* p) {
    unsigned a;
    asm("{ .reg .u64 t; cvta.to.shared.u64 t, %1; cvt.u32.u64 %0, t; }" : "=r"(a) : "l"(p));
    return a;
}
static __device__ __forceinline__ void cpa16(unsigned dst, const void* src) {
    asm volatile("cp.async.cg.shared.global [%0], [%1], 16;" :: "r"(dst), "l"(src));
}
#define CP_COMMIT() asm volatile("cp.async.commit_group;" ::: "memory")
#define CP_WAIT1()  asm volatile("cp.async.wait_group 1;" ::: "memory")
#define CP_WAIT0()  asm volatile("cp.async.wait_group 0;" ::: "memory")

static __device__ __forceinline__ void ldm4(unsigned* r, unsigned addr) {
    asm volatile("ldmatrix.sync.aligned.m8n8.x4.shared.b16 {%0,%1,%2,%3}, [%4];"
                 : "=r"(r[0]), "=r"(r[1]), "=r"(r[2]), "=r"(r[3]) : "r"(addr));
}
static __device__ __forceinline__ void ldm4t(unsigned* r, unsigned addr) {
    asm volatile("ldmatrix.sync.aligned.m8n8.x4.trans.shared.b16 {%0,%1,%2,%3}, [%4];"
                 : "=r"(r[0]), "=r"(r[1]), "=r"(r[2]), "=r"(r[3]) : "r"(addr));
}
static __device__ __forceinline__ void mma16816(float* d, const unsigned* a, const unsigned* b) {
    asm volatile("mma.sync.aligned.m16n8k16.row.col.f32.bf16.bf16.f32 "
                 "{%0,%1,%2,%3}, {%4,%5,%6,%7}, {%8,%9}, {%0,%1,%2,%3};"
                 : "+f"(d[0]), "+f"(d[1]), "+f"(d[2]), "+f"(d[3])
                 : "r"(a[0]), "r"(a[1]), "r"(a[2]), "r"(a[3]), "r"(b[0]), "r"(b[1]));
}

static __device__ __forceinline__ void wait_flag(const unsigned* p, unsigned want) {
    unsigned v;
    asm volatile("ld.acquire.gpu.global.u32 %0, [%1];" : "=r"(v) : "l"(p) : "memory");
    while ((int)v < (int)want) {
        __nanosleep(20);
        asm volatile("ld.acquire.gpu.global.u32 %0, [%1];" : "=r"(v) : "l"(p) : "memory");
    }
}
static __device__ __forceinline__ void st_release(unsigned* p, unsigned v) {
    asm volatile("st.release.gpu.global.u32 [%0], %1;" :: "l"(p), "r"(v) : "memory");
}

static __device__ __forceinline__ float fast_tanh(float v) {
    float e, r;
    asm("ex2.approx.f32 %0, %1;" : "=f"(e) : "f"(v * 2.885390081777927f));
    asm("rcp.approx.f32 %0, %1;" : "=f"(r) : "f"(e + 1.0f));
    return fmaf(-2.0f, r, 1.0f);
}
static __device__ __forceinline__ unsigned pack_bf2(__nv_bfloat16 a, __nv_bfloat16 b) {
    return (unsigned)__bfloat16_as_ushort(a) | ((unsigned)__bfloat16_as_ushort(b) << 16);
}

__device__ __forceinline__ void grid_barrier() {
    __syncthreads();
    __threadfence();
    if (threadIdx.x == 0) {
        unsigned gen = *((volatile unsigned*)&g_bar_gen);
        unsigned t = atomicAdd(&g_bar_count, 1u);
        if (t == NCTA - 1) {
            g_bar_count = 0;
            __threadfence();
            atomicAdd(&g_bar_gen, 1u);
        } else {
            while (*((volatile unsigned*)&g_bar_gen) == gen) { __nanosleep(16); }
        }
    }
    __syncthreads();
}

extern __shared__ char smem[];

__global__ void __launch_bounds__(256, 1)
rnn_hmma2_kernel(const float* __restrict__ x,    const float* __restrict__ W_hx,
                 const float* __restrict__ W_hh, const float* __restrict__ W_yh,
                 const float* __restrict__ b_h,  const float* __restrict__ b_y,
                 float* __restrict__ out)
{
    const unsigned sb = smem_u32(smem);
    const int tid  = threadIdx.x;
    const int lane = tid & 31;
    const int wid  = tid >> 5;
    const int nt   = blockIdx.x & 7;     // hidden tile (= the chunk this CTA produces)
    const int ct   = blockIdx.x >> 3;    // batch group 0..15
    const int n0   = nt * 64;
    const int c0   = ct * 64;            // global batch base (for x / out only)
    const int wm   = wid & 1;
    const int wn   = wid >> 1;

    // ---- Stage W_hh rows n0..n0+63 as bf16 hi/lo, 8 SW128 chunks ----
    for (int idx = tid; idx < 64 * Hn; idx += 256) {
        int r = idx >> 9, k = idx & 511;
        float w = W_hh[(n0 + r) * Hn + k];
        __nv_bfloat16 whi = __float2bfloat16(w);
        __nv_bfloat16 wlo = __float2bfloat16(w - __bfloat162float(whi));
        int c = k >> 6, kc = k & 63;
        unsigned off = (unsigned)(r * 128 + kc * 2);
        unsigned sw  = off ^ ((off >> 3) & 0x70);
        *(__nv_bfloat16*)(smem + SM_WHI + c * 8192 + sw) = whi;
        *(__nv_bfloat16*)(smem + SM_WLO + c * 8192 + sw) = wlo;
    }
    if (tid < 64)
        ((float2*)(smem + SM_WB))[tid] = make_float2(W_hx[n0 + tid], b_h[n0 + tid]);

    // ---- Zero OWN chunk region of buffer 0, then publish flag=1 ----
    {
        uint4 z = make_uint4(0, 0, 0, 0);
        uint4* ph = (uint4*)(g_hhi[0] + (size_t)ct * SHARD + nt * 4096);
        uint4* pl = (uint4*)(g_hlo[0] + (size_t)ct * SHARD + nt * 4096);
        ph[tid] = z; ph[tid + 256] = z;
        pl[tid] = z; pl[tid + 256] = z;
    }
    __threadfence();
    __syncthreads();                      // also covers W staging visibility
    if (tid == 0) st_release(&g_flag[ct][nt], 1u);

    // ---- cp.async slot precompute: 4 x 16B per thread per chunk ----
    const char* sbase[4]; unsigned dsw[4];
#pragma unroll
    for (int j = 0; j < 4; ++j) {
        int f = j * 256 + tid;
        int arr = f >> 9;                 // 0=hi 1=lo
        int ff = f & 511;
        int row = ff >> 3, seg = ff & 7;
        sbase[j] = (const char*)(arr ? g_hlo[0] : g_hhi[0])
                 + (size_t)ct * SHARD * 2 + (size_t)row * 128 + seg * 16;
        unsigned off = (unsigned)(row * 128 + seg * 16);
        dsw[j] = (unsigned)(arr * 8192) + (off ^ ((row & 7) << 4));
    }

    // ---- ldmatrix lane constants ----
    const int lane15 = lane & 15;
    const unsigned axor  = (unsigned)((lane & 7) << 4);
    const unsigned arow0 = (unsigned)((wm * 32 + lane15) * 128);
    const unsigned acx   = ((unsigned)((lane >> 4) * 16)) ^ axor;
    const unsigned browb = (unsigned)(lane15 * 128);
    const unsigned bcx   = ((unsigned)(wn * 32 + (lane >> 4) * 16)) ^ axor;

    const float2* WB = (const float2*)(smem + SM_WB);
    float* XS = (float*)(smem + SM_XS);

#define FILL(i2) do {                                                        \
        int cc = (nt + 1 + (i2)) & 7;                                        \
        if (cc != nt) wait_flag(&g_flag[ct][cc], (unsigned)(t + 1));         \
        unsigned db = sb + SM_A + (unsigned)(((i2) & 3) * 16384);            \
        size_t go = bufOff + (size_t)cc * 8192;                              \
        cpa16(db + dsw[0], sbase[0] + go);                                   \
        cpa16(db + dsw[1], sbase[1] + go);                                   \
        cpa16(db + dsw[2], sbase[2] + go);                                   \
        cpa16(db + dsw[3], sbase[3] + go);                                   \
        CP_COMMIT(); } while (0)

#define LDFRAG(s, ks) do {                                                   \
        unsigned colA = acx ^ (unsigned)((ks) * 32);                         \
        ldm4(ah[s][0], whb + arow0 + colA);                                  \
        ldm4(ah[s][1], whb + arow0 + 2048 + colA);                           \
        ldm4(al[s][0], wlb + arow0 + colA);                                  \
        ldm4(al[s][1], wlb + arow0 + 2048 + colA);                           \
        unsigned rB = hb + browb + (unsigned)((ks) * 2048) + bcx;            \
        ldm4t(bh[s], rB);                                                    \
        ldm4t(bl[s], rB + 8192); } while (0)

    for (int t = 0; t < Tn; ++t) {
        if (tid < 64) XS[tid] = x[(c0 + tid) * Tn + t];
        const size_t bufOff = (size_t)(t & 1) * (16 * SHARD * 2);

        FILL(0);
        FILL(1);

        float acc[2][2][4];
#pragma unroll
        for (int mi = 0; mi < 2; ++mi)
#pragma unroll
            for (int ni = 0; ni < 2; ++ni)
#pragma unroll
                for (int q = 0; q < 4; ++q) acc[mi][ni][q] = 0.f;

        for (int i = 0; i < 8; ++i) {
            const int c = (nt + 1 + i) & 7;
            if (i < 7) CP_WAIT1(); else CP_WAIT0();
            __syncthreads();

            const unsigned whb = sb + SM_WHI + (unsigned)(c * 8192);
            const unsigned wlb = whb + 65536;
            const unsigned hb  = sb + SM_A + (unsigned)((i & 3) * 16384);

            unsigned ah[2][2][4], al[2][2][4], bh[2][4], bl[2][4];
            LDFRAG(0, 0);
#pragma unroll
            for (int ks = 0; ks < 4; ++ks) {
                const int s = ks & 1;
                if (ks < 3) LDFRAG(s ^ 1, ks + 1);
#pragma unroll
                for (int mi = 0; mi < 2; ++mi)
#pragma unroll
                    for (int ni = 0; ni < 2; ++ni) {
                        mma16816(acc[mi][ni], ah[s][mi], bh[s] + ni * 2);
                        mma16816(acc[mi][ni], ah[s][mi], bl[s] + ni * 2);
                        mma16816(acc[mi][ni], al[s][mi], bh[s] + ni * 2);
                    }
            }
            if (i < 6) FILL(i + 2);
        }

        // ---- Epilogue: tanh + bf16 hi/lo split + store to ping-pong shard ----
        const int ob = (t + 1) & 1;
        __nv_bfloat16* oh = g_hhi[ob] + (size_t)ct * SHARD;
        __nv_bfloat16* ol = g_hlo[ob] + (size_t)ct * SHARD;
#pragma unroll
        for (int mi = 0; mi < 2; ++mi) {
            int rA = wm * 32 + mi * 16 + (lane >> 2);
            float2 wA  = WB[rA];
            float2 wB2 = WB[rA + 8];
#pragma unroll
            for (int ni = 0; ni < 2; ++ni) {
                int bl0 = wn * 16 + ni * 8 + 2 * (lane & 3);
                float xb0 = XS[bl0], xb1 = XS[bl0 + 1];
                float* a = acc[mi][ni];
                float y00 = fast_tanh(fmaf(wA.x,  xb0, a[0] + wA.y));
                float y01 = fast_tanh(fmaf(wA.x,  xb1, a[1] + wA.y));
                float y10 = fast_tanh(fmaf(wB2.x, xb0, a[2] + wB2.y));
                float y11 = fast_tanh(fmaf(wB2.x, xb1, a[3] + wB2.y));
                __nv_bfloat16 h00 = __float2bfloat16(y00), h01 = __float2bfloat16(y01);
                __nv_bfloat16 h10 = __float2bfloat16(y10), h11 = __float2bfloat16(y11);
                int o0 = (n0 + rA) * 64 + bl0;
                int o1 = o0 + 8 * 64;
                *(unsigned*)(oh + o0) = pack_bf2(h00, h01);
                *(unsigned*)(ol + o0) = pack_bf2(__float2bfloat16(y00 - __bfloat162float(h00)),
                                                 __float2bfloat16(y01 - __bfloat162float(h01)));
                *(unsigned*)(oh + o1) = pack_bf2(h10, h11);
                *(unsigned*)(ol + o1) = pack_bf2(__float2bfloat16(y10 - __bfloat162float(h10)),
                                                 __float2bfloat16(y11 - __bfloat162float(h11)));
            }
        }
        __threadfence();
        __syncthreads();
        if (tid == 0) st_release(&g_flag[ct][nt], (unsigned)(t + 2));
    }

    // ---- Drain, reset flags for next graph replay, final projection ----
    grid_barrier();
    if (tid == 0) *(volatile unsigned*)&g_flag[ct][nt] = 0u;

    if (nt == 0) {
        float* Wy = (float*)(smem + SM_WHI);       // main loop done; reuse W region
        for (int idx = tid; idx < On * Hn; idx += 256) Wy[idx] = W_yh[idx];
        __syncthreads();
        if (tid < 64) {
            float a10[On];
#pragma unroll
            for (int o = 0; o < On; ++o) a10[o] = b_y[o];
            const __nv_bfloat16* hh = g_hhi[0] + (size_t)ct * SHARD;
            const __nv_bfloat16* hl = g_hlo[0] + (size_t)ct * SHARD;
            for (int k = 0; k < Hn; ++k) {
                float hv = __bfloat162float(hh[k * 64 + tid])
                         + __bfloat162float(hl[k * 64 + tid]);
#pragma unroll
                for (int o = 0; o < On; ++o) a10[o] = fmaf(Wy[o * Hn + k], hv, a10[o]);
            }
            int b = c0 + tid;
#pragma unroll
            for (int o = 0; o < On; ++o) out[b * On + o] = a10[o];
        }
    }
}

extern "C" void kernel_launch(void* const* d_in, const int* in_sizes, int n_in,
                              void* d_out, int out_size) {
    (void)in_sizes; (void)n_in; (void)out_size;
    const float* x    = (const float*)d_in[0];
    const float* W_hx = (const float*)d_in[1];
    const float* W_hh = (const float*)d_in[2];
    const float* W_yh = (const float*)d_in[3];
    const float* b_h  = (const float*)d_in[4];
    const float* b_y  = (const float*)d_in[5];
    float* out = (float*)d_out;

    cudaFuncSetAttribute(rnn_hmma2_kernel, cudaFuncAttributeMaxDynamicSharedMemorySize, SM_TOTAL);
    rnn_hmma2_kernel<<<NCTA, 256, SM_TOTAL>>>(x, W_hx, W_hh, W_yh, b_h, b_y, out);
}

// round 8
// speedup vs baseline: 1.3865x; 1.3865x over previous
#include <cuda_runtime.h>
#include <cuda_bf16.h>

#define Hn 512
#define Bn 1024
#define Tn 512
#define On 10
#define NCTA 128

// SMEM byte offsets
#define SM_WHI 0        // 8 chunks x [64 rows x 64 k] bf16 SW128 = 65536
#define SM_WLO 65536
#define SM_A   131072   // 4 bufs x (hi 8KB + lo 8KB) = 65536
#define SM_WB  196608   // float2[64] {W_hx, b_h}
#define SM_XS  197120   // float[64]
#define SM_TOTAL 197376

__device__ __align__(16) __nv_bfloat16 g_hhi[2][Hn * Bn];  // [buf][k*Bn + b]
__device__ __align__(16) __nv_bfloat16 g_hlo[2][Hn * Bn];

struct alignas(128) CtBar { unsigned cnt; unsigned gen; unsigned pad[30]; };
__device__ CtBar g_ctbar[16];

static __device__ __forceinline__ unsigned smem_u32(const void* p) {
    unsigned a;
    asm("{ .reg .u64 t; cvta.to.shared.u64 t, %1; cvt.u32.u64 %0, t; }" : "=r"(a) : "l"(p));
    return a;
}
static __device__ __forceinline__ void cpa16(unsigned dst, const void* src) {
    asm volatile("cp.async.cg.shared.global [%0], [%1], 16;" :: "r"(dst), "l"(src));
}
#define CP_COMMIT() asm volatile("cp.async.commit_group;" ::: "memory")
#define CP_WAIT1()  asm volatile("cp.async.wait_group 1;" ::: "memory")
#define CP_WAIT0()  asm volatile("cp.async.wait_group 0;" ::: "memory")

static __device__ __forceinline__ void ldm4(unsigned* r, unsigned addr) {
    asm volatile("ldmatrix.sync.aligned.m8n8.x4.shared.b16 {%0,%1,%2,%3}, [%4];"
                 : "=r"(r[0]), "=r"(r[1]), "=r"(r[2]), "=r"(r[3]) : "r"(addr));
}
static __device__ __forceinline__ void ldm4t(unsigned* r, unsigned addr) {
    asm volatile("ldmatrix.sync.aligned.m8n8.x4.trans.shared.b16 {%0,%1,%2,%3}, [%4];"
                 : "=r"(r[0]), "=r"(r[1]), "=r"(r[2]), "=r"(r[3]) : "r"(addr));
}
static __device__ __forceinline__ void mma16816(float* d, const unsigned* a, const unsigned* b) {
    asm volatile("mma.sync.aligned.m16n8k16.row.col.f32.bf16.bf16.f32 "
                 "{%0,%1,%2,%3}, {%4,%5,%6,%7}, {%8,%9}, {%0,%1,%2,%3};"
                 : "+f"(d[0]), "+f"(d[1]), "+f"(d[2]), "+f"(d[3])
                 : "r"(a[0]), "r"(a[1]), "r"(a[2]), "r"(a[3]), "r"(b[0]), "r"(b[1]));
}

static __device__ __forceinline__ float fast_tanh(float v) {
    float e, r;
    asm("ex2.approx.f32 %0, %1;" : "=f"(e) : "f"(v * 2.885390081777927f));
    asm("rcp.approx.f32 %0, %1;" : "=f"(r) : "f"(e + 1.0f));
    return fmaf(-2.0f, r, 1.0f);
}
static __device__ __forceinline__ unsigned pack_bf2(__nv_bfloat16 a, __nv_bfloat16 b) {
    return (unsigned)__bfloat16_as_ushort(a) | ((unsigned)__bfloat16_as_ushort(b) << 16);
}

// 8-CTA barrier over the CTAs sharing one ct group (same pattern as the proven
// grid barrier, scoped to 8 arrivals on a padded per-ct cache line).
static __device__ __forceinline__ void ct_barrier(int ct) {
    __syncthreads();
    __threadfence();
    if (threadIdx.x == 0) {
        CtBar* cb = &g_ctbar[ct];
        unsigned gen = *((volatile unsigned*)&cb->gen);
        unsigned tkt = atomicAdd(&cb->cnt, 1u);
        if (tkt == 7u) {
            cb->cnt = 0;
            __threadfence();
            atomicAdd(&cb->gen, 1u);
        } else {
            while (*((volatile unsigned*)&cb->gen) == gen) { __nanosleep(16); }
        }
    }
    __syncthreads();
}

extern __shared__ char smem[];

__global__ void __launch_bounds__(256, 1)
rnn_hmma5_kernel(const float* __restrict__ x,    const float* __restrict__ W_hx,
                 const float* __restrict__ W_hh, const float* __restrict__ W_yh,
                 const float* __restrict__ b_h,  const float* __restrict__ b_y,
                 float* __restrict__ out)
{
    const unsigned sb = smem_u32(smem);
    const int tid  = threadIdx.x;
    const int lane = tid & 31;
    const int wid  = tid >> 5;
    const int nt   = blockIdx.x & 7;     // hidden tile 0..7
    const int ct   = blockIdx.x >> 3;    // batch group 0..15
    const int n0   = nt * 64;
    const int c0   = ct * 64;
    const int wm   = wid & 1;
    const int wn   = wid >> 1;

    // ---- Stage W_hh rows n0..n0+63 as bf16 hi/lo: 8 SW128 chunks [64r x 64k] ----
    for (int idx = tid; idx < 64 * Hn; idx += 256) {
        int r = idx >> 9, k = idx & 511;
        float w = W_hh[(n0 + r) * Hn + k];
        __nv_bfloat16 whi = __float2bfloat16(w);
        __nv_bfloat16 wlo = __float2bfloat16(w - __bfloat162float(whi));
        int c = k >> 6, kc = k & 63;
        unsigned off = (unsigned)(r * 128 + kc * 2);
        unsigned sw  = off ^ ((off >> 3) & 0x70);
        *(__nv_bfloat16*)(smem + SM_WHI + c * 8192 + sw) = whi;
        *(__nv_bfloat16*)(smem + SM_WLO + c * 8192 + sw) = wlo;
    }
    if (tid < 64)
        ((float2*)(smem + SM_WB))[tid] = make_float2(W_hx[n0 + tid], b_h[n0 + tid]);

    // ---- Zero own group-aligned region of buffer 0: rows n0..n0+63, cols c0..c0+63
    // (group-local so the 8-CTA barrier suffices to publish it) ----
    {
        uint4 z = make_uint4(0, 0, 0, 0);
#pragma unroll
        for (int p = 0; p < 2; ++p) {
            int item = tid + p * 256;        // 512 items: 64 rows x 8 uint4
            int r = item >> 3, q = item & 7;
            size_t off = (size_t)(n0 + r) * Bn + c0;   // elements
            ((uint4*)(g_hhi[0] + off))[q] = z;
            ((uint4*)(g_hlo[0] + off))[q] = z;
        }
    }

    // ---- cp.async slot precompute: 4 x 16B per thread per chunk ----
    const char* s0[4]; const char* s1[4]; unsigned dsw[4];
#pragma unroll
    for (int j = 0; j < 4; ++j) {
        int f = j * 256 + tid;
        int arr = f >> 9;               // 0=hi 1=lo
        int ff = f & 511;
        int row = ff >> 3, seg = ff & 7;
        size_t so = (size_t)row * (Bn * 2) + seg * 16 + (size_t)c0 * 2;
        s0[j] = (const char*)g_hhi[0] + so;   // arr==0
        if (arr) s0[j] = (const char*)g_hlo[0] + so;
        s1[j] = (const char*)g_hhi[1] + so;
        if (arr) s1[j] = (const char*)g_hlo[1] + so;
        unsigned off = (unsigned)(row * 128 + seg * 16);
        dsw[j] = (unsigned)(arr * 8192) + (off ^ ((row & 7) << 4));
    }

    // ---- ldmatrix lane constants (verified R4) ----
    const int lane15 = lane & 15;
    const unsigned axor  = (unsigned)((lane & 7) << 4);
    const unsigned arow0 = (unsigned)((wm * 32 + lane15) * 128);
    const unsigned acx   = ((unsigned)((lane >> 4) * 16)) ^ axor;
    const unsigned browb = (unsigned)(lane15 * 128);
    const unsigned bcx   = ((unsigned)(wn * 32 + (lane >> 4) * 16)) ^ axor;

    const float2* WB = (const float2*)(smem + SM_WB);
    float* XS = (float*)(smem + SM_XS);

    ct_barrier(ct);   // h0 zeros (group-local) + W staging visible

#define PREFETCH(ch, sp) do {                                     \
        unsigned db = sb + SM_A + (unsigned)(((ch) & 3) * 16384); \
        size_t go = (size_t)(ch) * 131072;                        \
        cpa16(db + dsw[0], (sp)[0] + go);                         \
        cpa16(db + dsw[1], (sp)[1] + go);                         \
        cpa16(db + dsw[2], (sp)[2] + go);                         \
        cpa16(db + dsw[3], (sp)[3] + go);                         \
        CP_COMMIT(); } while (0)

    for (int t = 0; t < Tn; ++t) {
        if (tid < 64) XS[tid] = x[(c0 + tid) * Tn + t];
        const char* const* sp = (t & 1) ? s1 : s0;
        PREFETCH(0, sp);
        PREFETCH(1, sp);

        float acc[2][2][4];
#pragma unroll
        for (int mi = 0; mi < 2; ++mi)
#pragma unroll
            for (int ni = 0; ni < 2; ++ni)
#pragma unroll
                for (int q = 0; q < 4; ++q) acc[mi][ni][q] = 0.f;

        for (int c = 0; c < 8; ++c) {
            if (c < 7) CP_WAIT1(); else CP_WAIT0();
            __syncthreads();

            unsigned whb = sb + SM_WHI + (unsigned)(c * 8192);
            unsigned wlb = whb + 65536;
            unsigned hb  = sb + SM_A + (unsigned)((c & 3) * 16384);

#pragma unroll
            for (int ks = 0; ks < 4; ++ks) {
                unsigned ah[2][4], al[2][4], bh[4], bl[4];
                unsigned colA = acx ^ (unsigned)(ks * 32);
                ldm4(ah[0], whb + arow0 + colA);
                ldm4(ah[1], whb + arow0 + 2048 + colA);
                ldm4(al[0], wlb + arow0 + colA);
                ldm4(al[1], wlb + arow0 + 2048 + colA);
                unsigned rB = hb + browb + (unsigned)(ks * 2048) + bcx;
                ldm4t(bh, rB);            // hi h
                ldm4t(bl, rB + 8192);     // lo h
#pragma unroll
                for (int mi = 0; mi < 2; ++mi)
#pragma unroll
                    for (int ni = 0; ni < 2; ++ni) {
                        mma16816(acc[mi][ni], ah[mi], bh + ni * 2);
                        mma16816(acc[mi][ni], ah[mi], bl + ni * 2);
                        mma16816(acc[mi][ni], al[mi], bh + ni * 2);
                    }
            }
            if (c < 6) PREFETCH(c + 2, sp);
        }

        // ---- Epilogue: tanh + bf16 hi/lo split + store to ping-pong buffer ----
        int ob = (t + 1) & 1;
        __nv_bfloat16* oh = g_hhi[ob];
        __nv_bfloat16* ol = g_hlo[ob];
#pragma unroll
        for (int mi = 0; mi < 2; ++mi) {
            int rA = wm * 32 + mi * 16 + (lane >> 2);     // local hidden row
            float2 wA  = WB[rA];
            float2 wB2 = WB[rA + 8];
#pragma unroll
            for (int ni = 0; ni < 2; ++ni) {
                int bl0 = wn * 16 + ni * 8 + 2 * (lane & 3);
                float xb0 = XS[bl0], xb1 = XS[bl0 + 1];
                float* a = acc[mi][ni];
                float y00 = fast_tanh(fmaf(wA.x,  xb0, a[0] + wA.y));
                float y01 = fast_tanh(fmaf(wA.x,  xb1, a[1] + wA.y));
                float y10 = fast_tanh(fmaf(wB2.x, xb0, a[2] + wB2.y));
                float y11 = fast_tanh(fmaf(wB2.x, xb1, a[3] + wB2.y));
                __nv_bfloat16 h00 = __float2bfloat16(y00), h01 = __float2bfloat16(y01);
                __nv_bfloat16 h10 = __float2bfloat16(y10), h11 = __float2bfloat16(y11);
                size_t o0 = (size_t)(n0 + rA) * Bn + (c0 + bl0);
                size_t o1 = o0 + (size_t)8 * Bn;
                *(unsigned*)(oh + o0) = pack_bf2(h00, h01);
                *(unsigned*)(ol + o0) = pack_bf2(__float2bfloat16(y00 - __bfloat162float(h00)),
                                                 __float2bfloat16(y01 - __bfloat162float(h01)));
                *(unsigned*)(oh + o1) = pack_bf2(h10, h11);
                *(unsigned*)(ol + o1) = pack_bf2(__float2bfloat16(y10 - __bfloat162float(h10)),
                                                 __float2bfloat16(y11 - __bfloat162float(h11)));
            }
        }
        ct_barrier(ct);   // publishes this step's h within the 8-CTA group
    }

    // ---- Final projection: out[b][o] = b_y[o] + sum_k W_yh[o][k] * h[k][b] ----
    // Final h is in buffer 0; columns c0..c0+63 were produced by this ct group.
    if (nt == 0) {
        float* Wy = (float*)(smem + SM_WHI);       // main loop done; reuse W region
        for (int idx = tid; idx < On * Hn; idx += 256) Wy[idx] = W_yh[idx];
        __syncthreads();
        if (tid < 64) {
            int b = c0 + tid;
            float a10[On];
#pragma unroll
            for (int o = 0; o < On; ++o) a10[o] = b_y[o];
            const __nv_bfloat16* hh = g_hhi[0];
            const __nv_bfloat16* hl = g_hlo[0];
            for (int k = 0; k < Hn; ++k) {
                float hv = __bfloat162float(hh[(size_t)k * Bn + b])
                         + __bfloat162float(hl[(size_t)k * Bn + b]);
#pragma unroll
                for (int o = 0; o < On; ++o) a10[o] = fmaf(Wy[o * Hn + k], hv, a10[o]);
            }
#pragma unroll
            for (int o = 0; o < On; ++o) out[b * On + o] = a10[o];
        }
    }
}

extern "C" void kernel_launch(void* const* d_in, const int* in_sizes, int n_in,
                              void* d_out, int out_size) {
    (void)in_sizes; (void)n_in; (void)out_size;
    const float* x    = (const float*)d_in[0];
    const float* W_hx = (const float*)d_in[1];
    const float* W_hh = (const float*)d_in[2];
    const float* W_yh = (const float*)d_in[3];
    const float* b_h  = (const float*)d_in[4];
    const float* b_y  = (const float*)d_in[5];
    float* out = (float*)d_out;

    cudaFuncSetAttribute(rnn_hmma5_kernel, cudaFuncAttributeMaxDynamicSharedMemorySize, SM_TOTAL);
    rnn_hmma5_kernel<<<NCTA, 256, SM_TOTAL>>>(x, W_hx, W_hh, W_yh, b_h, b_y, out);
}

// round 9
// speedup vs baseline: 2.0319x; 1.4655x over previous
#include <cuda_runtime.h>
#include <cuda_bf16.h>

#define Hn 512
#define Bn 1024
#define Tn 512
#define On 10
#define NCTA 128

// SMEM byte offsets
#define SM_WHI 0        // 8 chunks x [64 rows x 64 k] bf16 SW128 = 65536
#define SM_WLO 65536
#define SM_A   131072   // 4 bufs x (hi 8KB + lo 8KB) = 65536
#define SM_WB  196608   // float2[64] {W_hx, b_h}
#define SM_XS  197120   // float[64]
#define SM_TOTAL 197376

__device__ __align__(16) __nv_bfloat16 g_hhi[2][Hn * Bn];  // [buf][k*Bn + b]
__device__ __align__(16) __nv_bfloat16 g_hlo[2][Hn * Bn];

struct alignas(128) CtBar { unsigned cnt; unsigned gen; unsigned pad[30]; };
__device__ CtBar g_ctbar[16];

static __device__ __forceinline__ unsigned smem_u32(const void* p) {
    unsigned a;
    asm("{ .reg .u64 t; cvta.to.shared.u64 t, %1; cvt.u32.u64 %0, t; }" : "=r"(a) : "l"(p));
    return a;
}
static __device__ __forceinline__ void cpa16(unsigned dst, const void* src) {
    asm volatile("cp.async.cg.shared.global [%0], [%1], 16;" :: "r"(dst), "l"(src));
}
#define CP_COMMIT() asm volatile("cp.async.commit_group;" ::: "memory")
#define CP_WAIT1()  asm volatile("cp.async.wait_group 1;" ::: "memory")
#define CP_WAIT0()  asm volatile("cp.async.wait_group 0;" ::: "memory")

static __device__ __forceinline__ void ldm4(unsigned* r, unsigned addr) {
    asm volatile("ldmatrix.sync.aligned.m8n8.x4.shared.b16 {%0,%1,%2,%3}, [%4];"
                 : "=r"(r[0]), "=r"(r[1]), "=r"(r[2]), "=r"(r[3]) : "r"(addr));
}
static __device__ __forceinline__ void ldm4t(unsigned* r, unsigned addr) {
    asm volatile("ldmatrix.sync.aligned.m8n8.x4.trans.shared.b16 {%0,%1,%2,%3}, [%4];"
                 : "=r"(r[0]), "=r"(r[1]), "=r"(r[2]), "=r"(r[3]) : "r"(addr));
}
static __device__ __forceinline__ void mma16816(float* d, const unsigned* a, const unsigned* b) {
    asm volatile("mma.sync.aligned.m16n8k16.row.col.f32.bf16.bf16.f32 "
                 "{%0,%1,%2,%3}, {%4,%5,%6,%7}, {%8,%9}, {%0,%1,%2,%3};"
                 : "+f"(d[0]), "+f"(d[1]), "+f"(d[2]), "+f"(d[3])
                 : "r"(a[0]), "r"(a[1]), "r"(a[2]), "r"(a[3]), "r"(b[0]), "r"(b[1]));
}

static __device__ __forceinline__ float fast_tanh(float v) {
    float e, r;
    asm("ex2.approx.f32 %0, %1;" : "=f"(e) : "f"(v * 2.885390081777927f));
    asm("rcp.approx.f32 %0, %1;" : "=f"(r) : "f"(e + 1.0f));
    return fmaf(-2.0f, r, 1.0f);
}
static __device__ __forceinline__ unsigned pack_bf2(__nv_bfloat16 a, __nv_bfloat16 b) {
    return (unsigned)__bfloat16_as_ushort(a) | ((unsigned)__bfloat16_as_ushort(b) << 16);
}

// 8-CTA barrier over the CTAs sharing one ct group.
static __device__ __forceinline__ void ct_barrier(int ct) {
    __syncthreads();
    __threadfence();
    if (threadIdx.x == 0) {
        CtBar* cb = &g_ctbar[ct];
        unsigned gen = *((volatile unsigned*)&cb->gen);
        unsigned tkt = atomicAdd(&cb->cnt, 1u);
        if (tkt == 7u) {
            cb->cnt = 0;
            __threadfence();
            atomicAdd(&cb->gen, 1u);
        } else {
            while (*((volatile unsigned*)&cb->gen) == gen) { __nanosleep(16); }
        }
    }
    __syncthreads();
}

extern __shared__ char smem[];

__global__ void __launch_bounds__(256, 1)
rnn_hmma6_kernel(const float* __restrict__ x,    const float* __restrict__ W_hx,
                 const float* __restrict__ W_hh, const float* __restrict__ W_yh,
                 const float* __restrict__ b_h,  const float* __restrict__ b_y,
                 float* __restrict__ out)
{
    const unsigned sb = smem_u32(smem);
    const int tid  = threadIdx.x;
    const int lane = tid & 31;
    const int wid  = tid >> 5;
    const int nt   = blockIdx.x & 7;     // hidden tile 0..7
    const int ct   = blockIdx.x >> 3;    // batch group 0..15
    const int n0   = nt * 64;
    const int c0   = ct * 64;
    const int wm   = wid & 1;
    const int wn   = wid >> 1;

    // ---- Stage W_hh rows n0..n0+63 as bf16 hi/lo: 8 SW128 chunks [64r x 64k] ----
    for (int idx = tid; idx < 64 * Hn; idx += 256) {
        int r = idx >> 9, k = idx & 511;
        float w = W_hh[(n0 + r) * Hn + k];
        __nv_bfloat16 whi = __float2bfloat16(w);
        __nv_bfloat16 wlo = __float2bfloat16(w - __bfloat162float(whi));
        int c = k >> 6, kc = k & 63;
        unsigned off = (unsigned)(r * 128 + kc * 2);
        unsigned sw  = off ^ ((off >> 3) & 0x70);
        *(__nv_bfloat16*)(smem + SM_WHI + c * 8192 + sw) = whi;
        *(__nv_bfloat16*)(smem + SM_WLO + c * 8192 + sw) = wlo;
    }
    if (tid < 64)
        ((float2*)(smem + SM_WB))[tid] = make_float2(W_hx[n0 + tid], b_h[n0 + tid]);

    // ---- Zero own group-aligned region of buffer 0 (rows n0.., cols c0..) ----
    {
        uint4 z = make_uint4(0, 0, 0, 0);
#pragma unroll
        for (int p = 0; p < 2; ++p) {
            int item = tid + p * 256;        // 512 items: 64 rows x 8 uint4
            int r = item >> 3, q = item & 7;
            size_t off = (size_t)(n0 + r) * Bn + c0;
            ((uint4*)(g_hhi[0] + off))[q] = z;
            ((uint4*)(g_hlo[0] + off))[q] = z;
        }
    }

    // ---- cp.async slot precompute: 4 x 16B per thread per chunk ----
    const char* s0[4]; const char* s1[4]; unsigned dsw[4];
#pragma unroll
    for (int j = 0; j < 4; ++j) {
        int f = j * 256 + tid;
        int arr = f >> 9;               // 0=hi 1=lo
        int ff = f & 511;
        int row = ff >> 3, seg = ff & 7;
        size_t so = (size_t)row * (Bn * 2) + seg * 16 + (size_t)c0 * 2;
        s0[j] = (const char*)g_hhi[0] + so;
        if (arr) s0[j] = (const char*)g_hlo[0] + so;
        s1[j] = (const char*)g_hhi[1] + so;
        if (arr) s1[j] = (const char*)g_hlo[1] + so;
        unsigned off = (unsigned)(row * 128 + seg * 16);
        dsw[j] = (unsigned)(arr * 8192) + (off ^ ((row & 7) << 4));
    }

    // ---- ldmatrix lane constants (verified R4/R5) ----
    const int lane15 = lane & 15;
    const unsigned axor  = (unsigned)((lane & 7) << 4);
    const unsigned arow0 = (unsigned)((wm * 32 + lane15) * 128);
    const unsigned acx   = ((unsigned)((lane >> 4) * 16)) ^ axor;
    const unsigned browb = (unsigned)(lane15 * 128);
    const unsigned bcx   = ((unsigned)(wn * 32 + (lane >> 4) * 16)) ^ axor;

    const float2* WB = (const float2*)(smem + SM_WB);
    float* XS = (float*)(smem + SM_XS);

    ct_barrier(ct);   // h0 zeros (group-local) + W staging visible

#define PREFETCH(ch, sp) do {                                     \
        unsigned db = sb + SM_A + (unsigned)(((ch) & 3) * 16384); \
        size_t go = (size_t)(ch) * 131072;                        \
        cpa16(db + dsw[0], (sp)[0] + go);                         \
        cpa16(db + dsw[1], (sp)[1] + go);                         \
        cpa16(db + dsw[2], (sp)[2] + go);                         \
        cpa16(db + dsw[3], (sp)[3] + go);                         \
        CP_COMMIT(); } while (0)

#define LDFRAG(s, ks) do {                                                   \
        unsigned colA = acx ^ (unsigned)((ks) * 32);                         \
        ldm4(ah[s][0], whb + arow0 + colA);                                  \
        ldm4(ah[s][1], whb + arow0 + 2048 + colA);                           \
        ldm4(al[s][0], wlb + arow0 + colA);                                  \
        ldm4(al[s][1], wlb + arow0 + 2048 + colA);                           \
        unsigned rB = hb + browb + (unsigned)((ks) * 2048) + bcx;            \
        ldm4t(bh[s], rB);                                                    \
        ldm4t(bl[s], rB + 8192); } while (0)

    for (int t = 0; t < Tn; ++t) {
        if (tid < 64) XS[tid] = x[(c0 + tid) * Tn + t];
        const char* const* sp = (t & 1) ? s1 : s0;
        PREFETCH(0, sp);
        PREFETCH(1, sp);

        float acc[2][2][4];
#pragma unroll
        for (int mi = 0; mi < 2; ++mi)
#pragma unroll
            for (int ni = 0; ni < 2; ++ni)
#pragma unroll
                for (int q = 0; q < 4; ++q) acc[mi][ni][q] = 0.f;

        for (int c = 0; c < 8; ++c) {
            if (c < 7) CP_WAIT1(); else CP_WAIT0();
            __syncthreads();

            const unsigned whb = sb + SM_WHI + (unsigned)(c * 8192);
            const unsigned wlb = whb + 65536;
            const unsigned hb  = sb + SM_A + (unsigned)((c & 3) * 16384);

            unsigned ah[2][2][4], al[2][2][4], bh[2][4], bl[2][4];
            LDFRAG(0, 0);
#pragma unroll
            for (int ks = 0; ks < 4; ++ks) {
                const int s = ks & 1;
                if (ks < 3) LDFRAG(s ^ 1, ks + 1);   // overlap next LDSMs with MMAs
#pragma unroll
                for (int mi = 0; mi < 2; ++mi)
#pragma unroll
                    for (int ni = 0; ni < 2; ++ni) {
                        mma16816(acc[mi][ni], ah[s][mi], bh[s] + ni * 2);
                        mma16816(acc[mi][ni], ah[s][mi], bl[s] + ni * 2);
                        mma16816(acc[mi][ni], al[s][mi], bh[s] + ni * 2);
                    }
            }
            if (c < 6) PREFETCH(c + 2, sp);
        }

        // ---- Epilogue: tanh + bf16 hi/lo split + store to ping-pong buffer ----
        int ob = (t + 1) & 1;
        __nv_bfloat16* oh = g_hhi[ob];
        __nv_bfloat16* ol = g_hlo[ob];
#pragma unroll
        for (int mi = 0; mi < 2; ++mi) {
            int rA = wm * 32 + mi * 16 + (lane >> 2);     // local hidden row
            float2 wA  = WB[rA];
            float2 wB2 = WB[rA + 8];
#pragma unroll
            for (int ni = 0; ni < 2; ++ni) {
                int bl0 = wn * 16 + ni * 8 + 2 * (lane & 3);
                float xb0 = XS[bl0], xb1 = XS[bl0 + 1];
                float* a = acc[mi][ni];
                float y00 = fast_tanh(fmaf(wA.x,  xb0, a[0] + wA.y));
                float y01 = fast_tanh(fmaf(wA.x,  xb1, a[1] + wA.y));
                float y10 = fast_tanh(fmaf(wB2.x, xb0, a[2] + wB2.y));
                float y11 = fast_tanh(fmaf(wB2.x, xb1, a[3] + wB2.y));
                __nv_bfloat16 h00 = __float2bfloat16(y00), h01 = __float2bfloat16(y01);
                __nv_bfloat16 h10 = __float2bfloat16(y10), h11 = __float2bfloat16(y11);
                size_t o0 = (size_t)(n0 + rA) * Bn + (c0 + bl0);
                size_t o1 = o0 + (size_t)8 * Bn;
                *(unsigned*)(oh + o0) = pack_bf2(h00, h01);
                *(unsigned*)(ol + o0) = pack_bf2(__float2bfloat16(y00 - __bfloat162float(h00)),
                                                 __float2bfloat16(y01 - __bfloat162float(h01)));
                *(unsigned*)(oh + o1) = pack_bf2(h10, h11);
                *(unsigned*)(ol + o1) = pack_bf2(__float2bfloat16(y10 - __bfloat162float(h10)),
                                                 __float2bfloat16(y11 - __bfloat162float(h11)));
            }
        }
        ct_barrier(ct);   // publishes this step's h within the 8-CTA group
    }

    // ---- Final projection: out[b][o] = b_y[o] + sum_k W_yh[o][k] * h[k][b] ----
    if (nt == 0) {
        float* Wy = (float*)(smem + SM_WHI);       // main loop done; reuse W region
        for (int idx = tid; idx < On * Hn; idx += 256) Wy[idx] = W_yh[idx];
        __syncthreads();
        if (tid < 64) {
            int b = c0 + tid;
            float a10[On];
#pragma unroll
            for (int o = 0; o < On; ++o) a10[o] = b_y[o];
            const __nv_bfloat16* hh = g_hhi[0];
            const __nv_bfloat16* hl = g_hlo[0];
            for (int k = 0; k < Hn; ++k) {
                float hv = __bfloat162float(hh[(size_t)k * Bn + b])
                         + __bfloat162float(hl[(size_t)k * Bn + b]);
#pragma unroll
                for (int o = 0; o < On; ++o) a10[o] = fmaf(Wy[o * Hn + k], hv, a10[o]);
            }
#pragma unroll
            for (int o = 0; o < On; ++o) out[b * On + o] = a10[o];
        }
    }
}

extern "C" void kernel_launch(void* const* d_in, const int* in_sizes, int n_in,
                              void* d_out, int out_size) {
    (void)in_sizes; (void)n_in; (void)out_size;
    const float* x    = (const float*)d_in[0];
    const float* W_hx = (const float*)d_in[1];
    const float* W_hh = (const float*)d_in[2];
    const float* W_yh = (const float*)d_in[3];
    const float* b_h  = (const float*)d_in[4];
    const float* b_y  = (const float*)d_in[5];
    float* out = (float*)d_out;

    cudaFuncSetAttribute(rnn_hmma6_kernel, cudaFuncAttributeMaxDynamicSharedMemorySize, SM_TOTAL);
    rnn_hmma6_kernel<<<NCTA, 256, SM_TOTAL>>>(x, W_hx, W_hh, W_yh, b_h, b_y, out);
}

// round 10
// speedup vs baseline: 2.1786x; 1.0722x over previous
#include <cuda_runtime.h>
#include <cuda_bf16.h>

#define Hn 512
#define Bn 1024
#define Tn 512
#define On 10
#define NCTA 128

// SMEM byte offsets
#define SM_WHI 0        // 8 chunks x [64 rows x 64 k] bf16 SW128 = 65536
#define SM_WLO 65536
#define SM_A   131072   // 4 bufs x 16KB (hi 8K + lo 8K); half h owns bufs 2h,2h+1
#define SM_WB  196608   // float2[64] {W_hx, b_h}
#define SM_XS  197120   // float[64]
#define SM_TOTAL 197376

__device__ __align__(16) __nv_bfloat16 g_hhi[2][Hn * Bn];  // [buf][k*Bn + b]
__device__ __align__(16) __nv_bfloat16 g_hlo[2][Hn * Bn];

struct alignas(128) CtBar { unsigned cnt; unsigned gen; unsigned pad[30]; };
__device__ CtBar g_ctbar[16];

static __device__ __forceinline__ unsigned smem_u32(const void* p) {
    unsigned a;
    asm("{ .reg .u64 t; cvta.to.shared.u64 t, %1; cvt.u32.u64 %0, t; }" : "=r"(a) : "l"(p));
    return a;
}
static __device__ __forceinline__ void cpa16(unsigned dst, const void* src) {
    asm volatile("cp.async.cg.shared.global [%0], [%1], 16;" :: "r"(dst), "l"(src));
}
#define CP_COMMIT() asm volatile("cp.async.commit_group;" ::: "memory")
#define CP_WAIT1()  asm volatile("cp.async.wait_group 1;" ::: "memory")
#define CP_WAIT0()  asm volatile("cp.async.wait_group 0;" ::: "memory")

static __device__ __forceinline__ void ldm4(unsigned* r, unsigned addr) {
    asm volatile("ldmatrix.sync.aligned.m8n8.x4.shared.b16 {%0,%1,%2,%3}, [%4];"
                 : "=r"(r[0]), "=r"(r[1]), "=r"(r[2]), "=r"(r[3]) : "r"(addr));
}
static __device__ __forceinline__ void ldm4t(unsigned* r, unsigned addr) {
    asm volatile("ldmatrix.sync.aligned.m8n8.x4.trans.shared.b16 {%0,%1,%2,%3}, [%4];"
                 : "=r"(r[0]), "=r"(r[1]), "=r"(r[2]), "=r"(r[3]) : "r"(addr));
}
static __device__ __forceinline__ void mma16816(float* d, const unsigned* a, const unsigned* b) {
    asm volatile("mma.sync.aligned.m16n8k16.row.col.f32.bf16.bf16.f32 "
                 "{%0,%1,%2,%3}, {%4,%5,%6,%7}, {%8,%9}, {%0,%1,%2,%3};"
                 : "+f"(d[0]), "+f"(d[1]), "+f"(d[2]), "+f"(d[3])
                 : "r"(a[0]), "r"(a[1]), "r"(a[2]), "r"(a[3]), "r"(b[0]), "r"(b[1]));
}

static __device__ __forceinline__ float fast_tanh(float v) {
    float e, r;
    asm("ex2.approx.f32 %0, %1;" : "=f"(e) : "f"(v * 2.885390081777927f));
    asm("rcp.approx.f32 %0, %1;" : "=f"(r) : "f"(e + 1.0f));
    return fmaf(-2.0f, r, 1.0f);
}
static __device__ __forceinline__ unsigned pack_bf2(__nv_bfloat16 a, __nv_bfloat16 b) {
    return (unsigned)__bfloat16_as_ushort(a) | ((unsigned)__bfloat16_as_ushort(b) << 16);
}

// Per-half named barrier: id 1 (half 0) / id 2 (half 1), 256 threads each.
static __device__ __forceinline__ void half_bar(int half) {
    asm volatile("bar.sync %0, 256;" :: "r"(1 + half) : "memory");
}

// 8-CTA barrier over the CTAs sharing one ct group.
static __device__ __forceinline__ void ct_barrier(int ct) {
    __syncthreads();
    __threadfence();
    if (threadIdx.x == 0) {
        CtBar* cb = &g_ctbar[ct];
        unsigned gen = *((volatile unsigned*)&cb->gen);
        unsigned tkt = atomicAdd(&cb->cnt, 1u);
        if (tkt == 7u) {
            cb->cnt = 0;
            __threadfence();
            atomicAdd(&cb->gen, 1u);
        } else {
            while (*((volatile unsigned*)&cb->gen) == gen) { __nanosleep(16); }
        }
    }
    __syncthreads();
}

extern __shared__ char smem[];

__global__ void __launch_bounds__(512, 1)
rnn_hmma7_kernel(const float* __restrict__ x,    const float* __restrict__ W_hx,
                 const float* __restrict__ W_hh, const float* __restrict__ W_yh,
                 const float* __restrict__ b_h,  const float* __restrict__ b_y,
                 float* __restrict__ out)
{
    const unsigned sb = smem_u32(smem);
    const int tid  = threadIdx.x;
    const int lane = tid & 31;
    const int wid  = tid >> 5;
    const int half = wid >> 3;           // K half: 0 -> chunks 0..3, 1 -> chunks 4..7
    const int hwid = wid & 7;            // warp id within half (R9 roles)
    const int htid = tid & 255;          // thread id within half
    const int nt   = blockIdx.x & 7;     // hidden tile 0..7
    const int ct   = blockIdx.x >> 3;    // batch group 0..15
    const int n0   = nt * 64;
    const int c0   = ct * 64;
    const int wm   = hwid & 1;
    const int wn   = hwid >> 1;          // 0..3

    // ---- Stage W_hh rows n0..n0+63 as bf16 hi/lo: 8 SW128 chunks [64r x 64k] ----
    for (int idx = tid; idx < 64 * Hn; idx += 512) {
        int r = idx >> 9, k = idx & 511;
        float w = W_hh[(n0 + r) * Hn + k];
        __nv_bfloat16 whi = __float2bfloat16(w);
        __nv_bfloat16 wlo = __float2bfloat16(w - __bfloat162float(whi));
        int c = k >> 6, kc = k & 63;
        unsigned off = (unsigned)(r * 128 + kc * 2);
        unsigned sw  = off ^ ((off >> 3) & 0x70);
        *(__nv_bfloat16*)(smem + SM_WHI + c * 8192 + sw) = whi;
        *(__nv_bfloat16*)(smem + SM_WLO + c * 8192 + sw) = wlo;
    }
    if (tid < 64)
        ((float2*)(smem + SM_WB))[tid] = make_float2(W_hx[n0 + tid], b_h[n0 + tid]);

    // ---- Zero own group-aligned region of buffer 0 (rows n0.., cols c0..) ----
    {
        uint4 z = make_uint4(0, 0, 0, 0);
        int r = tid >> 3, q = tid & 7;        // 512 items = 64 rows x 8 uint4
        size_t off = (size_t)(n0 + r) * Bn + c0;
        ((uint4*)(g_hhi[0] + off))[q] = z;
        ((uint4*)(g_hlo[0] + off))[q] = z;
    }

    // ---- cp.async slot precompute: 4 x 16B per HALF-thread per chunk ----
    const char* s0[4]; const char* s1[4]; unsigned dsw[4];
#pragma unroll
    for (int j = 0; j < 4; ++j) {
        int f = j * 256 + htid;
        int arr = f >> 9;               // 0=hi 1=lo
        int ff = f & 511;
        int row = ff >> 3, seg = ff & 7;
        size_t so = (size_t)row * (Bn * 2) + seg * 16 + (size_t)c0 * 2;
        s0[j] = (const char*)g_hhi[0] + so;
        if (arr) s0[j] = (const char*)g_hlo[0] + so;
        s1[j] = (const char*)g_hhi[1] + so;
        if (arr) s1[j] = (const char*)g_hlo[1] + so;
        unsigned off = (unsigned)(row * 128 + seg * 16);
        dsw[j] = (unsigned)(arr * 8192) + (off ^ ((row & 7) << 4));
    }

    // ---- ldmatrix lane constants (identical to R4/R9) ----
    const int lane15 = lane & 15;
    const unsigned axor  = (unsigned)((lane & 7) << 4);
    const unsigned arow0 = (unsigned)((wm * 32 + lane15) * 128);
    const unsigned acx   = ((unsigned)((lane >> 4) * 16)) ^ axor;
    const unsigned browb = (unsigned)(lane15 * 128);
    const unsigned bcx   = ((unsigned)(wn * 32 + (lane >> 4) * 16)) ^ axor;

    const float2* WB = (const float2*)(smem + SM_WB);
    float* XS  = (float*)(smem + SM_XS);
    float* RED = (float*)(smem + SM_A);   // reduction scratch (reuses buf region)

    const int cbase = half * 4;           // first global chunk of this half
    const unsigned bufb = (unsigned)(half * 2);

    ct_barrier(ct);   // h0 zeros (group-local) + W staging visible

#define PFH(i, sp) do {                                                        \
        unsigned db = sb + SM_A + (bufb + ((i) & 1)) * 16384u;                 \
        size_t go = (size_t)(cbase + (i)) * 131072;                            \
        cpa16(db + dsw[0], (sp)[0] + go);                                      \
        cpa16(db + dsw[1], (sp)[1] + go);                                      \
        cpa16(db + dsw[2], (sp)[2] + go);                                      \
        cpa16(db + dsw[3], (sp)[3] + go);                                      \
        CP_COMMIT(); } while (0)

#define LDFRAG(s, ks) do {                                                     \
        unsigned colA = acx ^ (unsigned)((ks) * 32);                           \
        ldm4(ah[s][0], whb + arow0 + colA);                                    \
        ldm4(ah[s][1], whb + arow0 + 2048 + colA);                             \
        ldm4(al[s][0], wlb + arow0 + colA);                                    \
        ldm4(al[s][1], wlb + arow0 + 2048 + colA);                             \
        unsigned rB = hb + browb + (unsigned)((ks) * 2048) + bcx;              \
        ldm4t(bh[s], rB);                                                      \
        ldm4t(bl[s], rB + 8192); } while (0)

    for (int t = 0; t < Tn; ++t) {
        if (tid < 64) XS[tid] = x[(c0 + tid) * Tn + t];
        const char* const* sp = (t & 1) ? s1 : s0;
        PFH(0, sp);
        PFH(1, sp);

        float acc[2][2][4];
#pragma unroll
        for (int mi = 0; mi < 2; ++mi)
#pragma unroll
            for (int ni = 0; ni < 2; ++ni)
#pragma unroll
                for (int q = 0; q < 4; ++q) acc[mi][ni][q] = 0.f;

        for (int i = 0; i < 4; ++i) {
            if (i < 3) CP_WAIT1(); else CP_WAIT0();
            half_bar(half);               // cp.async data visible half-wide

            const int c = cbase + i;
            const unsigned whb = sb + SM_WHI + (unsigned)(c * 8192);
            const unsigned wlb = whb + 65536;
            const unsigned hb  = sb + SM_A + (bufb + (unsigned)(i & 1)) * 16384u;

            unsigned ah[2][2][4], al[2][2][4], bh[2][4], bl[2][4];
            LDFRAG(0, 0);
#pragma unroll
            for (int ks = 0; ks < 4; ++ks) {
                const int s = ks & 1;
                if (ks < 3) LDFRAG(s ^ 1, ks + 1);
#pragma unroll
                for (int mi = 0; mi < 2; ++mi)
#pragma unroll
                    for (int ni = 0; ni < 2; ++ni) {
                        mma16816(acc[mi][ni], ah[s][mi], bh[s] + ni * 2);
                        mma16816(acc[mi][ni], ah[s][mi], bl[s] + ni * 2);
                        mma16816(acc[mi][ni], al[s][mi], bh[s] + ni * 2);
                    }
            }
            half_bar(half);               // all reads of this buffer done
            if (i < 2) PFH(i + 2, sp);    // safe to overwrite buf (i&1)
        }

        // ---- Combine K halves: wk1 stores partials, wk0 accumulates ----
        __syncthreads();
        if (half == 1) {
#pragma unroll
            for (int mi = 0; mi < 2; ++mi)
#pragma unroll
                for (int ni = 0; ni < 2; ++ni)
#pragma unroll
                    for (int q = 0; q < 4; ++q)
                        RED[(hwid * 16 + (mi * 2 + ni) * 4 + q) * 32 + lane] = acc[mi][ni][q];
        }
        __syncthreads();

        if (half == 0) {
#pragma unroll
            for (int mi = 0; mi < 2; ++mi)
#pragma unroll
                for (int ni = 0; ni < 2; ++ni)
#pragma unroll
                    for (int q = 0; q < 4; ++q)
                        acc[mi][ni][q] += RED[(hwid * 16 + (mi * 2 + ni) * 4 + q) * 32 + lane];

            // ---- Epilogue: tanh + bf16 hi/lo split + store to ping-pong buffer ----
            int ob = (t + 1) & 1;
            __nv_bfloat16* oh = g_hhi[ob];
            __nv_bfloat16* ol = g_hlo[ob];
#pragma unroll
            for (int mi = 0; mi < 2; ++mi) {
                int rA = wm * 32 + mi * 16 + (lane >> 2);
                float2 wA  = WB[rA];
                float2 wB2 = WB[rA + 8];
#pragma unroll
                for (int ni = 0; ni < 2; ++ni) {
                    int bl0 = wn * 16 + ni * 8 + 2 * (lane & 3);
                    float xb0 = XS[bl0], xb1 = XS[bl0 + 1];
                    float* a = acc[mi][ni];
                    float y00 = fast_tanh(fmaf(wA.x,  xb0, a[0] + wA.y));
                    float y01 = fast_tanh(fmaf(wA.x,  xb1, a[1] + wA.y));
                    float y10 = fast_tanh(fmaf(wB2.x, xb0, a[2] + wB2.y));
                    float y11 = fast_tanh(fmaf(wB2.x, xb1, a[3] + wB2.y));
                    __nv_bfloat16 h00 = __float2bfloat16(y00), h01 = __float2bfloat16(y01);
                    __nv_bfloat16 h10 = __float2bfloat16(y10), h11 = __float2bfloat16(y11);
                    size_t o0 = (size_t)(n0 + rA) * Bn + (c0 + bl0);
                    size_t o1 = o0 + (size_t)8 * Bn;
                    *(unsigned*)(oh + o0) = pack_bf2(h00, h01);
                    *(unsigned*)(ol + o0) = pack_bf2(__float2bfloat16(y00 - __bfloat162float(h00)),
                                                     __float2bfloat16(y01 - __bfloat162float(h01)));
                    *(unsigned*)(oh + o1) = pack_bf2(h10, h11);
                    *(unsigned*)(ol + o1) = pack_bf2(__float2bfloat16(y10 - __bfloat162float(h10)),
                                                     __float2bfloat16(y11 - __bfloat162float(h11)));
                }
            }
        }
        ct_barrier(ct);   // publishes this step's h within the 8-CTA group
    }

    // ---- Final projection: out[b][o] = b_y[o] + sum_k W_yh[o][k] * h[k][b] ----
    if (nt == 0) {
        float* Wy = (float*)(smem + SM_WHI);       // main loop done; reuse W region
        for (int idx = tid; idx < On * Hn; idx += 512) Wy[idx] = W_yh[idx];
        __syncthreads();
        if (tid < 64) {
            int b = c0 + tid;
            float a10[On];
#pragma unroll
            for (int o = 0; o < On; ++o) a10[o] = b_y[o];
            const __nv_bfloat16* hh = g_hhi[0];
            const __nv_bfloat16* hl = g_hlo[0];
            for (int k = 0; k < Hn; ++k) {
                float hv = __bfloat162float(hh[(size_t)k * Bn + b])
                         + __bfloat162float(hl[(size_t)k * Bn + b]);
#pragma unroll
                for (int o = 0; o < On; ++o) a10[o] = fmaf(Wy[o * Hn + k], hv, a10[o]);
            }
#pragma unroll
            for (int o = 0; o < On; ++o) out[b * On + o] = a10[o];
        }
    }
}

extern "C" void kernel_launch(void* const* d_in, const int* in_sizes, int n_in,
                              void* d_out, int out_size) {
    (void)in_sizes; (void)n_in; (void)out_size;
    const float* x    = (const float*)d_in[0];
    const float* W_hx = (const float*)d_in[1];
    const float* W_hh = (const float*)d_in[2];
    const float* W_yh = (const float*)d_in[3];
    const float* b_h  = (const float*)d_in[4];
    const float* b_y  = (const float*)d_in[5];
    float* out = (float*)d_out;

    cudaFuncSetAttribute(rnn_hmma7_kernel, cudaFuncAttributeMaxDynamicSharedMemorySize, SM_TOTAL);
    rnn_hmma7_kernel<<<NCTA, 512, SM_TOTAL>>>(x, W_hx, W_hh, W_yh, b_h, b_y, out);
}